// round 1
// baseline (speedup 1.0000x reference)
#include <cuda_runtime.h>

#define DIMN 384
#define MAXBATCH 1024
#define BM 64
#define BN 64
#define BK 32

// Scratch (no cudaMalloc allowed)
__device__ float g_P[DIMN * DIMN];      // prod_k (1 - W_k)
__device__ float g_C[DIMN * DIMN];      // accumulated bias term
__device__ float g_cbar[DIMN];          // sum_i r[i] * C[i,j]
__device__ float g_t[MAXBATCH * DIMN];  // pooled intermediate

// ---------------------------------------------------------------------------
// Kernel 1: elementwise precompute of P and C over the block chain.
// M_k = M_{k-1}*(1-W_k) - b_k  =>  M = M0*P - C,
//   P = prod(1-W_k),  C_k = C_{k-1}*(1-W_k) + b_k.
// ---------------------------------------------------------------------------
__global__ void prep_kernel(const float* __restrict__ W,
                            const float* __restrict__ Bb,
                            int nblocks) {
    int idx = blockIdx.x * blockDim.x + threadIdx.x;
    if (idx >= DIMN * DIMN) return;
    float p = 1.0f, c = 0.0f;
    for (int k = 0; k < nblocks; k++) {
        float om = 1.0f - W[k * DIMN * DIMN + idx];
        float b  = Bb[k * DIMN * DIMN + idx];
        p *= om;
        c = c * om + b;
    }
    g_P[idx] = p;
    g_C[idx] = c;
}

// ---------------------------------------------------------------------------
// Kernel 2: cbar[j] = sum_i r[i] * C[i,j].  One CTA, 384 threads.
// ---------------------------------------------------------------------------
__global__ void cbar_kernel(const float* __restrict__ rw) {
    int j = threadIdx.x;
    if (j >= DIMN) return;
    float s = 0.0f;
#pragma unroll 8
    for (int i = 0; i < DIMN; i++)
        s += rw[i] * g_C[i * DIMN + j];
    g_cbar[j] = s;
}

// ---------------------------------------------------------------------------
// Kernel 3: GEMM A.
//   t[b,j] = v2[b,j] * ( sum_i (r[i]*v1[b,i]) * P[i,j] ) - cbar[j]
// A = (r ⊙ v1) [1024 x 384] row-major, B = P [384 x 384] row-major.
// 64x64 tile / CTA, 256 threads, 4x4 per-thread register tile, BK=32.
// ---------------------------------------------------------------------------
__global__ __launch_bounds__(256)
void gemmA_kernel(const float* __restrict__ v1,
                  const float* __restrict__ v2,
                  const float* __restrict__ rw) {
    __shared__ float As[BK][BM];
    __shared__ float Bs[BK][BN];

    const int tid = threadIdx.x;
    const int tx = tid & 15;   // col group
    const int ty = tid >> 4;   // row group
    const int m0 = blockIdx.y * BM;
    const int n0 = blockIdx.x * BN;

    float acc[4][4] = {};

    for (int k0 = 0; k0 < DIMN; k0 += BK) {
        // Load A tile (64 x 32), scaled by row_weights, store transposed.
#pragma unroll
        for (int rep = 0; rep < 2; rep++) {
            int t = tid + rep * 256;        // float4 index in [0,512)
            int r = t >> 3, c4 = t & 7;
            float4 v = *(const float4*)&v1[(m0 + r) * DIMN + k0 + c4 * 4];
            float4 w = *(const float4*)&rw[k0 + c4 * 4];
            As[c4 * 4 + 0][r] = v.x * w.x;
            As[c4 * 4 + 1][r] = v.y * w.y;
            As[c4 * 4 + 2][r] = v.z * w.z;
            As[c4 * 4 + 3][r] = v.w * w.w;
        }
        // Load B tile (32 x 64) from P, direct (row-major matches).
#pragma unroll
        for (int rep = 0; rep < 2; rep++) {
            int t = tid + rep * 256;
            int r = t >> 4, c4 = t & 15;
            *(float4*)&Bs[r][c4 * 4] =
                *(const float4*)&g_P[(k0 + r) * DIMN + n0 + c4 * 4];
        }
        __syncthreads();

#pragma unroll
        for (int k = 0; k < BK; k++) {
            float4 a = *(const float4*)&As[k][ty * 4];
            float4 b = *(const float4*)&Bs[k][tx * 4];
            float ar[4] = {a.x, a.y, a.z, a.w};
            float br[4] = {b.x, b.y, b.z, b.w};
#pragma unroll
            for (int m = 0; m < 4; m++)
#pragma unroll
                for (int n = 0; n < 4; n++)
                    acc[m][n] += ar[m] * br[n];
        }
        __syncthreads();
    }

    // Epilogue: t = v2 * acc - cbar  (vectorized over the 4 contiguous cols)
    const int col = n0 + tx * 4;
    float4 cb = *(const float4*)&g_cbar[col];
#pragma unroll
    for (int m = 0; m < 4; m++) {
        int row = m0 + ty * 4 + m;
        float4 v2v = *(const float4*)&v2[row * DIMN + col];
        float4 o;
        o.x = v2v.x * acc[m][0] - cb.x;
        o.y = v2v.y * acc[m][1] - cb.y;
        o.z = v2v.z * acc[m][2] - cb.z;
        o.w = v2v.w * acc[m][3] - cb.w;
        *(float4*)&g_t[row * DIMN + col] = o;
    }
}

// ---------------------------------------------------------------------------
// Kernel 4: GEMM B.
//   out[b,n] = sum_j t[b,j] * lin_W[n,j] + lin_b[n]
// B[k=j][n] = lin_W[n][j]: load lin_W rows (contiguous in j), store transposed.
// ---------------------------------------------------------------------------
__global__ __launch_bounds__(256)
void gemmB_kernel(const float* __restrict__ linW,
                  const float* __restrict__ linb,
                  float* __restrict__ out) {
    __shared__ float As[BK][BM];
    __shared__ float Bs[BK][BN];

    const int tid = threadIdx.x;
    const int tx = tid & 15;
    const int ty = tid >> 4;
    const int m0 = blockIdx.y * BM;
    const int n0 = blockIdx.x * BN;

    float acc[4][4] = {};

    for (int k0 = 0; k0 < DIMN; k0 += BK) {
        // Load A tile (64 x 32) from g_t, store transposed.
#pragma unroll
        for (int rep = 0; rep < 2; rep++) {
            int t = tid + rep * 256;
            int r = t >> 3, c4 = t & 7;
            float4 v = *(const float4*)&g_t[(m0 + r) * DIMN + k0 + c4 * 4];
            As[c4 * 4 + 0][r] = v.x;
            As[c4 * 4 + 1][r] = v.y;
            As[c4 * 4 + 2][r] = v.z;
            As[c4 * 4 + 3][r] = v.w;
        }
        // Load B tile: Bs[jj][nn] = linW[(n0+nn)*DIMN + k0+jj]
#pragma unroll
        for (int rep = 0; rep < 2; rep++) {
            int t = tid + rep * 256;
            int nn = t >> 3, j4 = t & 7;
            float4 v = *(const float4*)&linW[(n0 + nn) * DIMN + k0 + j4 * 4];
            Bs[j4 * 4 + 0][nn] = v.x;
            Bs[j4 * 4 + 1][nn] = v.y;
            Bs[j4 * 4 + 2][nn] = v.z;
            Bs[j4 * 4 + 3][nn] = v.w;
        }
        __syncthreads();

#pragma unroll
        for (int k = 0; k < BK; k++) {
            float4 a = *(const float4*)&As[k][ty * 4];
            float4 b = *(const float4*)&Bs[k][tx * 4];
            float ar[4] = {a.x, a.y, a.z, a.w};
            float br[4] = {b.x, b.y, b.z, b.w};
#pragma unroll
            for (int m = 0; m < 4; m++)
#pragma unroll
                for (int n = 0; n < 4; n++)
                    acc[m][n] += ar[m] * br[n];
        }
        __syncthreads();
    }

    const int col = n0 + tx * 4;
    float4 lb = *(const float4*)&linb[col];
#pragma unroll
    for (int m = 0; m < 4; m++) {
        int row = m0 + ty * 4 + m;
        float4 o;
        o.x = acc[m][0] + lb.x;
        o.y = acc[m][1] + lb.y;
        o.z = acc[m][2] + lb.z;
        o.w = acc[m][3] + lb.w;
        *(float4*)&out[row * DIMN + col] = o;
    }
}

// ---------------------------------------------------------------------------
// Launch
// Inputs (metadata order): v1, v2, block_W, block_b, row_weights, lin_W, lin_b
// ---------------------------------------------------------------------------
extern "C" void kernel_launch(void* const* d_in, const int* in_sizes, int n_in,
                              void* d_out, int out_size) {
    const float* v1   = (const float*)d_in[0];
    const float* v2   = (const float*)d_in[1];
    const float* bW   = (const float*)d_in[2];
    const float* bB   = (const float*)d_in[3];
    const float* rw   = (const float*)d_in[4];
    const float* linW = (const float*)d_in[5];
    const float* linb = (const float*)d_in[6];
    float* out = (float*)d_out;

    const int nblocks = in_sizes[2] / (DIMN * DIMN);
    const int batch   = in_sizes[0] / DIMN;

    // 1) P / C precompute
    prep_kernel<<<(DIMN * DIMN + 255) / 256, 256>>>(bW, bB, nblocks);
    // 2) cbar reduction
    cbar_kernel<<<1, DIMN>>>(rw);
    // 3) GEMM A: t = v2 * ((r.v1) @ P) - cbar
    dim3 gridA(DIMN / BN, batch / BM);
    gemmA_kernel<<<gridA, 256>>>(v1, v2, rw);
    // 4) GEMM B: out = t @ linW^T + linb
    gemmB_kernel<<<gridA, 256>>>(linW, linb, out);
}

// round 2
// speedup vs baseline: 1.4070x; 1.4070x over previous
#include <cuda_runtime.h>
#include <cstdint>

#define DIMN 384
#define MAXBATCH 1024
#define BM 64
#define BN 64
#define BK 32
#define AS_STRIDE 36   // [m][k] padded: frag banks (4g+t4+ks)%32 all distinct
#define BS_STRIDE 72   // [k][n] padded: frag banks (8t4+n)%32 all distinct

// Scratch (no cudaMalloc allowed)
__device__ float g_P[DIMN * DIMN];      // prod_k (1 - W_k)
__device__ float g_C[DIMN * DIMN];      // accumulated bias term
__device__ float g_cbar[DIMN];          // sum_i r[i] * C[i,j]
__device__ float g_t[MAXBATCH * DIMN];  // pooled intermediate

__device__ __forceinline__ uint32_t f2tf32(float x) {
    uint32_t y;
    asm("cvt.rna.tf32.f32 %0, %1;" : "=r"(y) : "f"(x));
    return y;
}

__device__ __forceinline__ void mma8(float* d, const uint32_t* a, const uint32_t* b) {
    asm volatile(
        "mma.sync.aligned.m16n8k8.row.col.f32.tf32.tf32.f32 "
        "{%0,%1,%2,%3}, {%4,%5,%6,%7}, {%8,%9}, {%0,%1,%2,%3};"
        : "+f"(d[0]), "+f"(d[1]), "+f"(d[2]), "+f"(d[3])
        : "r"(a[0]), "r"(a[1]), "r"(a[2]), "r"(a[3]),
          "r"(b[0]), "r"(b[1]));
}

// ---------------------------------------------------------------------------
// Kernel 1: P = prod(1-W_k), C_k = C_{k-1}*(1-W_k) + b_k  (elementwise)
// ---------------------------------------------------------------------------
__global__ void prep_kernel(const float* __restrict__ W,
                            const float* __restrict__ Bb,
                            int nblocks) {
    int idx = blockIdx.x * blockDim.x + threadIdx.x;
    if (idx >= DIMN * DIMN) return;
    float p = 1.0f, c = 0.0f;
    for (int k = 0; k < nblocks; k++) {
        float om = 1.0f - W[k * DIMN * DIMN + idx];
        float b  = Bb[k * DIMN * DIMN + idx];
        p *= om;
        c = c * om + b;
    }
    g_P[idx] = p;
    g_C[idx] = c;
}

// ---------------------------------------------------------------------------
// Kernel 2: cbar[j] = sum_i r[i] * C[i,j]
// ---------------------------------------------------------------------------
__global__ void cbar_kernel(const float* __restrict__ rw) {
    int j = threadIdx.x;
    if (j >= DIMN) return;
    float s = 0.0f;
#pragma unroll 8
    for (int i = 0; i < DIMN; i++)
        s += rw[i] * g_C[i * DIMN + j];
    g_cbar[j] = s;
}

// ---------------------------------------------------------------------------
// tf32 tensor-core GEMM, 64x64 tile / CTA, 8 warps (warp tile 16x32).
// MODE 0: t = v2 .* ((rw.*v1) @ P) - cbar     (A=v1, Bm=g_P row-major [k][n])
// MODE 1: out = (g_t @ linW^T) + linb         (A=g_t, Bm=linW row-major [n][k])
// ---------------------------------------------------------------------------
template <int MODE>
__global__ __launch_bounds__(256)
void mma_gemm(const float* __restrict__ A,
              const float* __restrict__ Bm,
              const float* __restrict__ rw,
              const float* __restrict__ v2,
              const float* __restrict__ addv,
              float* __restrict__ Out) {
    __shared__ __align__(16) uint32_t As[BM][AS_STRIDE];
    __shared__ __align__(16) uint32_t Bs[BK][BS_STRIDE];

    const int tid  = threadIdx.x;
    const int lane = tid & 31;
    const int wid  = tid >> 5;
    const int wm   = wid & 3;    // warp row group (16 rows each)
    const int wn   = wid >> 2;   // warp col half (32 cols each)
    const int g    = lane >> 2;  // groupID
    const int t4   = lane & 3;   // threadID_in_group
    const int m0   = blockIdx.y * BM;
    const int n0   = blockIdx.x * BN;

    // load-thread mappings
    const int ar  = tid >> 3;   // A row (0..31, +32 on rep)
    const int ac  = tid & 7;    // A k-float4
    const int pkr = tid >> 4;   // P k-row (0..15, +16 on rep)
    const int pc  = tid & 15;   // P n-float4
    const int lnn = tid & 63;   // linW n index
    const int ljc = tid >> 6;   // linW j-float4 (0..3, +4 on rep)

    float acc[4][4];
#pragma unroll
    for (int i = 0; i < 4; i++)
#pragma unroll
        for (int j = 0; j < 4; j++) acc[i][j] = 0.f;

    float4 pa[2], pb[2], pw[2];

    // prologue: prefetch stage 0
#pragma unroll
    for (int rep = 0; rep < 2; rep++) {
        int r = ar + rep * 32;
        pa[rep] = *(const float4*)&A[(m0 + r) * DIMN + ac * 4];
        if (MODE == 0) pw[rep] = *(const float4*)&rw[ac * 4];
    }
#pragma unroll
    for (int rep = 0; rep < 2; rep++) {
        if (MODE == 0) {
            int kr = pkr + rep * 16;
            pb[rep] = *(const float4*)&Bm[kr * DIMN + n0 + pc * 4];
        } else {
            int jc = ljc + rep * 4;
            pb[rep] = *(const float4*)&Bm[(n0 + lnn) * DIMN + jc * 4];
        }
    }

    const int NSTAGE = DIMN / BK;  // 12
    for (int s = 0; s < NSTAGE; s++) {
        __syncthreads();  // previous compute done before overwriting smem

        // store current stage (convert to tf32 at store)
#pragma unroll
        for (int rep = 0; rep < 2; rep++) {
            int r = ar + rep * 32;
            float4 v = pa[rep];
            if (MODE == 0) {
                float4 w = pw[rep];
                v.x *= w.x; v.y *= w.y; v.z *= w.z; v.w *= w.w;
            }
            uint4 u = make_uint4(f2tf32(v.x), f2tf32(v.y), f2tf32(v.z), f2tf32(v.w));
            *(uint4*)&As[r][ac * 4] = u;
        }
#pragma unroll
        for (int rep = 0; rep < 2; rep++) {
            float4 v = pb[rep];
            if (MODE == 0) {
                int kr = pkr + rep * 16;
                uint4 u = make_uint4(f2tf32(v.x), f2tf32(v.y), f2tf32(v.z), f2tf32(v.w));
                *(uint4*)&Bs[kr][pc * 4] = u;
            } else {
                int jc = ljc + rep * 4;
                Bs[jc * 4 + 0][lnn] = f2tf32(v.x);
                Bs[jc * 4 + 1][lnn] = f2tf32(v.y);
                Bs[jc * 4 + 2][lnn] = f2tf32(v.z);
                Bs[jc * 4 + 3][lnn] = f2tf32(v.w);
            }
        }

        // prefetch next stage (overlaps with compute below)
        if (s + 1 < NSTAGE) {
            const int k0 = (s + 1) * BK;
#pragma unroll
            for (int rep = 0; rep < 2; rep++) {
                int r = ar + rep * 32;
                pa[rep] = *(const float4*)&A[(m0 + r) * DIMN + k0 + ac * 4];
                if (MODE == 0) pw[rep] = *(const float4*)&rw[k0 + ac * 4];
            }
#pragma unroll
            for (int rep = 0; rep < 2; rep++) {
                if (MODE == 0) {
                    int kr = pkr + rep * 16;
                    pb[rep] = *(const float4*)&Bm[(k0 + kr) * DIMN + n0 + pc * 4];
                } else {
                    int jc = ljc + rep * 4;
                    pb[rep] = *(const float4*)&Bm[(n0 + lnn) * DIMN + k0 + jc * 4];
                }
            }
        }
        __syncthreads();

        // compute: 4 k8-steps on this stage
#pragma unroll
        for (int ks = 0; ks < BK; ks += 8) {
            uint32_t a[4];
            a[0] = As[wm * 16 + g    ][ks + t4    ];
            a[1] = As[wm * 16 + g + 8][ks + t4    ];
            a[2] = As[wm * 16 + g    ][ks + t4 + 4];
            a[3] = As[wm * 16 + g + 8][ks + t4 + 4];
#pragma unroll
            for (int nt = 0; nt < 4; nt++) {
                int nn = wn * 32 + nt * 8 + g;
                uint32_t b[2];
                b[0] = Bs[ks + t4    ][nn];
                b[1] = Bs[ks + t4 + 4][nn];
                mma8(acc[nt], a, b);
            }
        }
    }

    // epilogue: c0:(g,2t4) c1:(g,2t4+1) c2:(g+8,2t4) c3:(g+8,2t4+1)
    const int r0 = m0 + wm * 16 + g;
#pragma unroll
    for (int nt = 0; nt < 4; nt++) {
        int col = n0 + wn * 32 + nt * 8 + 2 * t4;
        float2 ad = *(const float2*)&addv[col];
        if (MODE == 0) {
            float2 va = *(const float2*)&v2[r0 * DIMN + col];
            float2 vb = *(const float2*)&v2[(r0 + 8) * DIMN + col];
            float2 o0 = make_float2(va.x * acc[nt][0] - ad.x,
                                    va.y * acc[nt][1] - ad.y);
            float2 o1 = make_float2(vb.x * acc[nt][2] - ad.x,
                                    vb.y * acc[nt][3] - ad.y);
            *(float2*)&Out[r0 * DIMN + col]       = o0;
            *(float2*)&Out[(r0 + 8) * DIMN + col] = o1;
        } else {
            *(float2*)&Out[r0 * DIMN + col] =
                make_float2(acc[nt][0] + ad.x, acc[nt][1] + ad.y);
            *(float2*)&Out[(r0 + 8) * DIMN + col] =
                make_float2(acc[nt][2] + ad.x, acc[nt][3] + ad.y);
        }
    }
}

// ---------------------------------------------------------------------------
// Launch. Inputs: v1, v2, block_W, block_b, row_weights, lin_W, lin_b
// ---------------------------------------------------------------------------
extern "C" void kernel_launch(void* const* d_in, const int* in_sizes, int n_in,
                              void* d_out, int out_size) {
    const float* v1   = (const float*)d_in[0];
    const float* v2   = (const float*)d_in[1];
    const float* bW   = (const float*)d_in[2];
    const float* bB   = (const float*)d_in[3];
    const float* rw   = (const float*)d_in[4];
    const float* linW = (const float*)d_in[5];
    const float* linb = (const float*)d_in[6];
    float* out = (float*)d_out;

    const int nblocks = in_sizes[2] / (DIMN * DIMN);
    const int batch   = in_sizes[0] / DIMN;

    float* gP = nullptr; float* gT = nullptr;
    cudaGetSymbolAddress((void**)&gP, g_P);
    cudaGetSymbolAddress((void**)&gT, g_t);
    float* gC; cudaGetSymbolAddress((void**)&gC, g_C);
    float* gcb; cudaGetSymbolAddress((void**)&gcb, g_cbar);

    prep_kernel<<<(DIMN * DIMN + 255) / 256, 256>>>(bW, bB, nblocks);
    cbar_kernel<<<1, DIMN>>>(rw);

    dim3 grid(DIMN / BN, batch / BM);
    mma_gemm<0><<<grid, 256>>>(v1, gP, rw, v2, gcb, gT);
    mma_gemm<1><<<grid, 256>>>(gT, linW, nullptr, nullptr, linb, out);
}